// round 1
// baseline (speedup 1.0000x reference)
#include <cuda_runtime.h>

#define H  64
#define LL 2048
#define NB 256
#define VOCAB 64

// -------- device-global scratch (no runtime allocation allowed) --------
__device__ __align__(16) float g_ktab[VOCAB * H];   // normalized k per vocab id
__device__ __align__(16) float g_vtab[VOCAB * H];   // v per vocab id
__device__ __align__(16) float g_qtab[VOCAB * H];   // q per vocab id
__device__ __align__(16) float g_KK[VOCAB * VOCAB]; // Gram of normalized k table
__device__ __align__(16) float g_Wcomb[H * H];      // Wout @ Wrp
__device__ __align__(16) float g_bcomb[H];          // Wout @ brp + bout

// ======================================================================
// P1: per-vocab encode (embed -> FF -> residual -> LN -> k/v/q tables)
// grid 64, block 128
// ======================================================================
__global__ void precompute_tables(
    const float* __restrict__ embed, const float* __restrict__ W1,
    const float* __restrict__ b1, const float* __restrict__ W2,
    const float* __restrict__ b2, const float* __restrict__ gamma,
    const float* __restrict__ beta, const float* __restrict__ Wk,
    const float* __restrict__ Wv, const float* __restrict__ Wq)
{
    const int v = blockIdx.x, tid = threadIdx.x;
    __shared__ float e[H], f1[2 * H], h[H], hs[H];
    __shared__ float s_mu, s_rstd, s_kinv;

    if (tid < H) e[tid] = embed[v * H + tid];
    __syncthreads();

    // ff1 = relu(W1 e + b1), all 128 threads
    {
        float a = b1[tid];
        const float* w = W1 + tid * H;
        #pragma unroll
        for (int k = 0; k < H; k++) a = fmaf(w[k], e[k], a);
        f1[tid] = fmaxf(a, 0.0f);
    }
    __syncthreads();

    // h = e + W2 ff1 + b2
    if (tid < H) {
        float a = b2[tid];
        const float* w = W2 + tid * 2 * H;
        #pragma unroll
        for (int j = 0; j < 2 * H; j++) a = fmaf(w[j], f1[j], a);
        h[tid] = e[tid] + a;
    }
    __syncthreads();

    // LayerNorm stats (biased var, eps 1e-5)
    if (tid < 32) {
        float x = h[tid] + h[tid + 32];
        #pragma unroll
        for (int o = 16; o; o >>= 1) x += __shfl_xor_sync(0xffffffffu, x, o);
        float mu = x * (1.0f / H);
        float c0 = h[tid] - mu, c1 = h[tid + 32] - mu;
        float vv = c0 * c0 + c1 * c1;
        #pragma unroll
        for (int o = 16; o; o >>= 1) vv += __shfl_xor_sync(0xffffffffu, vv, o);
        if (tid == 0) { s_mu = mu; s_rstd = rsqrtf(vv * (1.0f / H) + 1e-5f); }
    }
    __syncthreads();
    if (tid < H) hs[tid] = (h[tid] - s_mu) * s_rstd * gamma[tid] + beta[tid];
    __syncthreads();

    // projections: threads [0,64) -> k & q ; threads [64,128) -> v
    if (tid < H) {
        float a = 0.f, q = 0.f;
        const float* wk = Wk + tid * H;
        const float* wq = Wq + tid * H;
        #pragma unroll
        for (int j = 0; j < H; j++) {
            a = fmaf(wk[j], hs[j], a);
            q = fmaf(wq[j], hs[j], q);
        }
        h[tid] = a;                 // raw (unnormalized) k
        g_qtab[v * H + tid] = q;
    } else {
        const int i = tid - H;
        float a = 0.f;
        const float* wv = Wv + i * H;
        #pragma unroll
        for (int j = 0; j < H; j++) a = fmaf(wv[j], hs[j], a);
        g_vtab[v * H + i] = a;
    }
    __syncthreads();

    // k normalization: k / max(||k||, 1e-12)
    if (tid < 32) {
        float n = h[tid] * h[tid] + h[tid + 32] * h[tid + 32];
        #pragma unroll
        for (int o = 16; o; o >>= 1) n += __shfl_xor_sync(0xffffffffu, n, o);
        if (tid == 0) s_kinv = 1.0f / fmaxf(sqrtf(n), 1e-12f);
    }
    __syncthreads();
    if (tid < H) g_ktab[v * H + tid] = h[tid] * s_kinv;
}

// ======================================================================
// P2: Gram matrix KK = ktab ktab^T ; Wcomb = Wout @ Wrp ; bcomb
// grid 64, block 64
// ======================================================================
__global__ void precompute_misc(
    const float* __restrict__ Wrp, const float* __restrict__ brp,
    const float* __restrict__ Wout, const float* __restrict__ bout)
{
    const int i = blockIdx.x, j = threadIdx.x;
    float a = 0.f, w = 0.f;
    #pragma unroll
    for (int l = 0; l < H; l++) {
        a = fmaf(g_ktab[i * H + l], g_ktab[j * H + l], a);
        w = fmaf(Wout[i * H + l], Wrp[l * H + j], w);
    }
    g_KK[i * H + j] = a;
    g_Wcomb[i * H + j] = w;
    if (j == 0) {
        float bb = bout[i];
        #pragma unroll
        for (int l = 0; l < H; l++) bb = fmaf(Wout[i * H + l], brp[l], bb);
        g_bcomb[i] = bb;
    }
}

// ======================================================================
// Scan: one warp per batch. Backward vector recurrence, chunked by 8 so
// one butterfly round serves 8 steps; Gram-table forward substitution
// recovers the exact sequential s_t values.
// grid 256, block 32
// ======================================================================
__global__ void __launch_bounds__(32) scan_kernel(
    const int* __restrict__ seq, float* __restrict__ out)
{
    __shared__ __align__(16) float sk[VOCAB * H];
    __shared__ __align__(16) float sv[VOCAB * H];
    __shared__ __align__(16) int   sseq[LL];
    __shared__ float smq[H];

    const int b = blockIdx.x;
    const int lane = threadIdx.x;

    // stage tables + this batch's sequence into shared
    {
        const float4* kg = (const float4*)g_ktab;
        const float4* vg = (const float4*)g_vtab;
        float4* ksh = (float4*)sk;
        float4* vsh = (float4*)sv;
        for (int i = lane; i < VOCAB * H / 4; i += 32) { ksh[i] = kg[i]; vsh[i] = vg[i]; }
        const int4* sg = (const int4*)(seq + b * LL);
        int4* ssh = (int4*)sseq;
        for (int i = lane; i < LL / 4; i += 32) ssh[i] = sg[i];
    }
    __syncwarp();

    float2 p, acc;
    acc.x = 0.f; acc.y = 0.f;
    {
        const int qi = sseq[LL - 1];
        p = *(const float2*)&g_qtab[qi * H + 2 * lane];
    }

    // ---- 7 single steps: t = 2046 .. 2040 ----
    for (int t = LL - 2; t >= LL - 8; --t) {
        const int idx = sseq[t];
        const float2 k = *(const float2*)&sk[idx * H + 2 * lane];
        float s = k.x * p.x + k.y * p.y;
        #pragma unroll
        for (int o = 16; o; o >>= 1) s += __shfl_xor_sync(0xffffffffu, s, o);
        const float2 vv = *(const float2*)&sv[idx * H + 2 * lane];
        acc.x = fmaf(s, vv.x, acc.x); acc.y = fmaf(s, vv.y, acc.y);
        p.x = fmaf(-s, k.x, p.x);     p.y = fmaf(-s, k.y, p.y);
    }

    // ---- 255 groups of 8: t in [base, base+7], processed descending ----
    for (int base = LL - 16; base >= 0; base -= 8) {
        int idx[8];
        #pragma unroll
        for (int j = 0; j < 8; j++) idx[j] = sseq[base + 7 - j];  // j=0 is largest t

        float2 kk[8];
        #pragma unroll
        for (int j = 0; j < 8; j++)
            kk[j] = *(const float2*)&sk[idx[j] * H + 2 * lane];

        // Gram gathers (broadcast LDG, hidden behind the shuffle round)
        float G[28];
        #pragma unroll
        for (int j = 1; j < 8; j++)
            #pragma unroll
            for (int m = 0; m < j; m++)
                G[j * (j - 1) / 2 + m] = g_KK[idx[j] * VOCAB + idx[m]];

        // all 8 dots against p_in
        float d[8];
        #pragma unroll
        for (int j = 0; j < 8; j++) d[j] = kk[j].x * p.x + kk[j].y * p.y;

        // one butterfly round reduces all 8 dots
        #pragma unroll
        for (int o = 16; o; o >>= 1) {
            #pragma unroll
            for (int j = 0; j < 8; j++) d[j] += __shfl_xor_sync(0xffffffffu, d[j], o);
        }

        // forward substitution: s_j = d_j - sum_{m<j} (k_j . k_m) s_m
        float s[8];
        #pragma unroll
        for (int j = 0; j < 8; j++) {
            float a = d[j];
            #pragma unroll
            for (int m = 0; m < j; m++) a = fmaf(-G[j * (j - 1) / 2 + m], s[m], a);
            s[j] = a;
        }

        // p_out = p_in - sum_j s_j k_j
        #pragma unroll
        for (int j = 0; j < 8; j++) {
            p.x = fmaf(-s[j], kk[j].x, p.x);
            p.y = fmaf(-s[j], kk[j].y, p.y);
        }
        // Mq accumulation (off critical path)
        #pragma unroll
        for (int j = 0; j < 8; j++) {
            const float2 vv = *(const float2*)&sv[idx[j] * H + 2 * lane];
            acc.x = fmaf(s[j], vv.x, acc.x);
            acc.y = fmaf(s[j], vv.y, acc.y);
        }
    }

    // ---- epilogue: out = Wcomb @ (Mq) + bcomb ----
    smq[2 * lane]     = acc.x;
    smq[2 * lane + 1] = acc.y;
    __syncwarp();
    #pragma unroll
    for (int r = 0; r < 2; r++) {
        const int i = lane + 32 * r;
        float a = g_bcomb[i];
        const float* w = g_Wcomb + i * H;
        #pragma unroll
        for (int j = 0; j < H; j++) a = fmaf(w[j], smq[j], a);
        out[b * H + i] = a;
    }
}

// ======================================================================
extern "C" void kernel_launch(void* const* d_in, const int* in_sizes, int n_in,
                              void* d_out, int out_size)
{
    (void)in_sizes; (void)n_in; (void)out_size;
    const int*   seq   = (const int*)  d_in[0];
    const float* embed = (const float*)d_in[1];
    const float* W1    = (const float*)d_in[2];
    const float* b1    = (const float*)d_in[3];
    const float* W2    = (const float*)d_in[4];
    const float* b2    = (const float*)d_in[5];
    const float* gamma = (const float*)d_in[6];
    const float* beta  = (const float*)d_in[7];
    const float* Wk    = (const float*)d_in[8];
    const float* Wv    = (const float*)d_in[9];
    const float* Wq    = (const float*)d_in[10];
    const float* Wrp   = (const float*)d_in[11];
    const float* brp   = (const float*)d_in[12];
    const float* Wout  = (const float*)d_in[13];
    const float* bout  = (const float*)d_in[14];

    precompute_tables<<<VOCAB, 128>>>(embed, W1, b1, W2, b2, gamma, beta, Wk, Wv, Wq);
    precompute_misc<<<VOCAB, H>>>(Wrp, brp, Wout, bout);
    scan_kernel<<<NB, 32>>>(seq, (float*)d_out);
}

// round 3
// speedup vs baseline: 1.2523x; 1.2523x over previous
#include <cuda_runtime.h>

#define H  64
#define LL 2048
#define NB 256
#define VOCAB 64
#define FULL 0xffffffffu

// -------- device-global scratch (no runtime allocation allowed) --------
__device__ __align__(16) float g_ktab[VOCAB * H];   // normalized k per vocab id
__device__ __align__(16) float g_vtab[VOCAB * H];   // v per vocab id
__device__ __align__(16) float g_qtab[VOCAB * H];   // q per vocab id
__device__ __align__(16) float g_KK[VOCAB * VOCAB]; // Gram of normalized k table
__device__ __align__(16) float g_Wcomb[H * H];      // Wout @ Wrp
__device__ __align__(16) float g_bcomb[H];          // Wout @ brp + bout

__device__ __forceinline__ float bfly_sum(float v) {
    #pragma unroll
    for (int o = 16; o; o >>= 1) v += __shfl_xor_sync(FULL, v, o);
    return v;
}

// ======================================================================
// P1: per-vocab encode (embed -> FF -> residual -> LN -> k/v/q tables)
// grid 64, block 128.  float4 loads + split accumulators to kill chains.
// ======================================================================
__global__ void precompute_tables(
    const float* __restrict__ embed, const float* __restrict__ W1,
    const float* __restrict__ b1, const float* __restrict__ W2,
    const float* __restrict__ b2, const float* __restrict__ gamma,
    const float* __restrict__ beta, const float* __restrict__ Wk,
    const float* __restrict__ Wv, const float* __restrict__ Wq)
{
    const int v = blockIdx.x, tid = threadIdx.x;
    __shared__ __align__(16) float e[H], f1[2 * H], h[H], hs[H];
    __shared__ float s_mu, s_rstd, s_kinv;

    if (tid < H) e[tid] = embed[v * H + tid];
    __syncthreads();

    // ff1 = relu(W1 e + b1)
    {
        const float4* w4 = (const float4*)(W1 + tid * H);
        const float4* e4 = (const float4*)e;
        float a0 = 0.f, a1 = 0.f, a2 = 0.f, a3 = 0.f;
        #pragma unroll
        for (int i = 0; i < 16; i++) {
            float4 w = w4[i], ee = e4[i];
            a0 = fmaf(w.x, ee.x, a0); a1 = fmaf(w.y, ee.y, a1);
            a2 = fmaf(w.z, ee.z, a2); a3 = fmaf(w.w, ee.w, a3);
        }
        f1[tid] = fmaxf((a0 + a1) + (a2 + a3) + b1[tid], 0.0f);
    }
    __syncthreads();

    // h = e + W2 ff1 + b2
    if (tid < H) {
        const float4* w4 = (const float4*)(W2 + tid * 2 * H);
        const float4* f4 = (const float4*)f1;
        float a0 = 0.f, a1 = 0.f, a2 = 0.f, a3 = 0.f;
        float b0 = 0.f, c1 = 0.f, c2 = 0.f, b3 = 0.f;
        #pragma unroll
        for (int i = 0; i < 32; i += 2) {
            float4 w = w4[i], ff = f4[i];
            a0 = fmaf(w.x, ff.x, a0); a1 = fmaf(w.y, ff.y, a1);
            a2 = fmaf(w.z, ff.z, a2); a3 = fmaf(w.w, ff.w, a3);
            float4 w2_ = w4[i + 1], ff2 = f4[i + 1];
            b0 = fmaf(w2_.x, ff2.x, b0); c1 = fmaf(w2_.y, ff2.y, c1);
            c2 = fmaf(w2_.z, ff2.z, c2); b3 = fmaf(w2_.w, ff2.w, b3);
        }
        h[tid] = e[tid] + ((a0 + a1) + (a2 + a3)) + ((b0 + c1) + (c2 + b3)) + b2[tid];
    }
    __syncthreads();

    // LayerNorm stats (biased var, eps 1e-5)
    if (tid < 32) {
        float x = bfly_sum(h[tid] + h[tid + 32]);
        float mu = x * (1.0f / H);
        float c0 = h[tid] - mu, c1_ = h[tid + 32] - mu;
        float vv = bfly_sum(c0 * c0 + c1_ * c1_);
        if (tid == 0) { s_mu = mu; s_rstd = rsqrtf(vv * (1.0f / H) + 1e-5f); }
    }
    __syncthreads();
    if (tid < H) hs[tid] = (h[tid] - s_mu) * s_rstd * gamma[tid] + beta[tid];
    __syncthreads();

    // projections: threads [0,64) -> k & q ; threads [64,128) -> v
    if (tid < H) {
        const float4* wk4 = (const float4*)(Wk + tid * H);
        const float4* wq4 = (const float4*)(Wq + tid * H);
        const float4* h4 = (const float4*)hs;
        float k0 = 0.f, k1 = 0.f, k2 = 0.f, k3 = 0.f;
        float q0 = 0.f, q1 = 0.f, q2 = 0.f, q3 = 0.f;
        #pragma unroll
        for (int i = 0; i < 16; i++) {
            float4 wk = wk4[i], wq = wq4[i], hh = h4[i];
            k0 = fmaf(wk.x, hh.x, k0); k1 = fmaf(wk.y, hh.y, k1);
            k2 = fmaf(wk.z, hh.z, k2); k3 = fmaf(wk.w, hh.w, k3);
            q0 = fmaf(wq.x, hh.x, q0); q1 = fmaf(wq.y, hh.y, q1);
            q2 = fmaf(wq.z, hh.z, q2); q3 = fmaf(wq.w, hh.w, q3);
        }
        h[tid] = (k0 + k1) + (k2 + k3);   // raw k
        g_qtab[v * H + tid] = (q0 + q1) + (q2 + q3);
    } else {
        const int i = tid - H;
        const float4* wv4 = (const float4*)(Wv + i * H);
        const float4* h4 = (const float4*)hs;
        float a0 = 0.f, a1 = 0.f, a2 = 0.f, a3 = 0.f;
        #pragma unroll
        for (int j = 0; j < 16; j++) {
            float4 w = wv4[j], hh = h4[j];
            a0 = fmaf(w.x, hh.x, a0); a1 = fmaf(w.y, hh.y, a1);
            a2 = fmaf(w.z, hh.z, a2); a3 = fmaf(w.w, hh.w, a3);
        }
        g_vtab[v * H + i] = (a0 + a1) + (a2 + a3);
    }
    __syncthreads();

    // k normalization: k / max(||k||, 1e-12)
    if (tid < 32) {
        float n = bfly_sum(h[tid] * h[tid] + h[tid + 32] * h[tid + 32]);
        if (tid == 0) s_kinv = 1.0f / fmaxf(sqrtf(n), 1e-12f);
    }
    __syncthreads();
    if (tid < H) g_ktab[v * H + tid] = h[tid] * s_kinv;
}

// ======================================================================
// P2: Gram matrix KK = ktab ktab^T ; Wcomb = Wout @ Wrp ; bcomb
// grid 64, block 64
// ======================================================================
__global__ void precompute_misc(
    const float* __restrict__ Wrp, const float* __restrict__ brp,
    const float* __restrict__ Wout, const float* __restrict__ bout)
{
    const int i = blockIdx.x, j = threadIdx.x;
    const float4* ki4 = (const float4*)(g_ktab + i * H);
    const float4* kj4 = (const float4*)(g_ktab + j * H);
    float a0 = 0.f, a1 = 0.f, a2 = 0.f, a3 = 0.f;
    float w = 0.f, w1 = 0.f;
    #pragma unroll
    for (int l = 0; l < 16; l++) {
        float4 ka = ki4[l], kb = kj4[l];
        a0 = fmaf(ka.x, kb.x, a0); a1 = fmaf(ka.y, kb.y, a1);
        a2 = fmaf(ka.z, kb.z, a2); a3 = fmaf(ka.w, kb.w, a3);
    }
    #pragma unroll
    for (int l = 0; l < H; l += 2) {
        w  = fmaf(Wout[i * H + l],     Wrp[l * H + j],       w);
        w1 = fmaf(Wout[i * H + l + 1], Wrp[(l + 1) * H + j], w1);
    }
    g_KK[i * H + j] = (a0 + a1) + (a2 + a3);
    g_Wcomb[i * H + j] = w + w1;
    if (j == 0) {
        float bb = bout[i], bb1 = 0.f;
        #pragma unroll
        for (int l = 0; l < H; l += 2) {
            bb  = fmaf(Wout[i * H + l],     brp[l],     bb);
            bb1 = fmaf(Wout[i * H + l + 1], brp[l + 1], bb1);
        }
        g_bcomb[i] = bb + bb1;
    }
}

// ======================================================================
// Scan: one warp per batch. Backward vector recurrence, chunked by 8.
// Merged multi-value shuffle reduction (24 SHFL/group vs 40); Gram table
// in smem; G/v prefetched into the tree's stall shadow.
// grid 256, block 32
// ======================================================================
__global__ void __launch_bounds__(32) scan_kernel(
    const int* __restrict__ seq, float* __restrict__ out)
{
    __shared__ __align__(16) float sk[VOCAB * H];        // 16 KB
    __shared__ __align__(16) float sKK[VOCAB * VOCAB];   // 16 KB
    __shared__ __align__(16) unsigned char sseq[LL];     // 2 KB (tokens < 64)
    __shared__ float smq[H];

    const int b = blockIdx.x;
    const int lane = threadIdx.x;

    // stage tables + packed sequence into shared
    {
        const float4* kg = (const float4*)g_ktab;
        const float4* gg = (const float4*)g_KK;
        float4* ksh = (float4*)sk;
        float4* gsh = (float4*)sKK;
        #pragma unroll
        for (int i = lane; i < VOCAB * H / 4; i += 32) { ksh[i] = kg[i]; gsh[i] = gg[i]; }
        const int4* sg = (const int4*)(seq + b * LL);
        uchar4* ssh = (uchar4*)sseq;
        #pragma unroll
        for (int i = lane; i < LL / 4; i += 32) {
            int4 t = sg[i];
            ssh[i] = make_uchar4((unsigned char)t.x, (unsigned char)t.y,
                                 (unsigned char)t.z, (unsigned char)t.w);
        }
    }
    __syncwarp();

    float2 p, acc;
    acc.x = 0.f; acc.y = 0.f;
    {
        const int qi = sseq[LL - 1];
        p = __ldg((const float2*)&g_qtab[qi * H + 2 * lane]);
    }

    // ---- 7 single steps: t = 2046 .. 2040 ----
    #pragma unroll
    for (int t = LL - 2; t >= LL - 8; --t) {
        const int idx = (int)sseq[t];
        const float2 k = *(const float2*)&sk[idx * H + 2 * lane];
        float s = bfly_sum(fmaf(k.y, p.y, k.x * p.x));
        const float2 vv = __ldg((const float2*)&g_vtab[idx * H + 2 * lane]);
        acc.x = fmaf(s, vv.x, acc.x); acc.y = fmaf(s, vv.y, acc.y);
        p.x = fmaf(-s, k.x, p.x);     p.y = fmaf(-s, k.y, p.y);
    }

    const bool lo16 = (lane < 16);
    const bool lo8  = ((lane & 8) == 0);
    const bool lo4  = ((lane & 4) == 0);

    // ---- 255 groups of 8: t in [base, base+7], processed descending ----
    for (int base = LL - 16; base >= 0; base -= 8) {
        int off[8];          // token * 64 (row offset in sk / sKK)
        #pragma unroll
        for (int j = 0; j < 8; j++) off[j] = ((int)sseq[base + 7 - j]) << 6;

        float2 kk[8];
        #pragma unroll
        for (int j = 0; j < 8; j++)
            kk[j] = *(const float2*)&sk[off[j] + 2 * lane];

        // Gram gathers from smem (issued before the tree; land in its shadow)
        float G[28];
        #pragma unroll
        for (int j = 1; j < 8; j++)
            #pragma unroll
            for (int m = 0; m < j; m++)
                G[j * (j - 1) / 2 + m] = sKK[off[j] + (off[m] >> 6)];

        // v prefetch (LDG via L2; consumed after substitution)
        float2 vv[8];
        #pragma unroll
        for (int j = 0; j < 8; j++)
            vv[j] = __ldg((const float2*)&g_vtab[off[j] + 2 * lane]);

        // per-lane dot partials against p_in
        float d[8];
        #pragma unroll
        for (int j = 0; j < 8; j++) d[j] = fmaf(kk[j].y, p.y, kk[j].x * p.x);

        // merged reduce-and-concentrate tree: 16 SHFL + 7 SEL
        #pragma unroll
        for (int j = 0; j < 8; j++) d[j] += __shfl_xor_sync(FULL, d[j], 16);
        float m0 = lo16 ? d[0] : d[1];
        float m1 = lo16 ? d[2] : d[3];
        float m2 = lo16 ? d[4] : d[5];
        float m3 = lo16 ? d[6] : d[7];
        m0 += __shfl_xor_sync(FULL, m0, 8);
        m1 += __shfl_xor_sync(FULL, m1, 8);
        m2 += __shfl_xor_sync(FULL, m2, 8);
        m3 += __shfl_xor_sync(FULL, m3, 8);
        float n0 = lo8 ? m0 : m1;
        float n1 = lo8 ? m2 : m3;
        n0 += __shfl_xor_sync(FULL, n0, 4);
        n1 += __shfl_xor_sync(FULL, n1, 4);
        float r = lo4 ? n0 : n1;
        r += __shfl_xor_sync(FULL, r, 2);
        r += __shfl_xor_sync(FULL, r, 1);
        // group g = lane>>2 holds dot bitrev3(g); broadcast totals
        float dt[8];
        dt[0] = __shfl_sync(FULL, r, 0);
        dt[1] = __shfl_sync(FULL, r, 16);
        dt[2] = __shfl_sync(FULL, r, 8);
        dt[3] = __shfl_sync(FULL, r, 24);
        dt[4] = __shfl_sync(FULL, r, 4);
        dt[5] = __shfl_sync(FULL, r, 20);
        dt[6] = __shfl_sync(FULL, r, 12);
        dt[7] = __shfl_sync(FULL, r, 28);

        // forward substitution: s_j = d_j - sum_{m<j} (k_j . k_m) s_m
        float s[8];
        #pragma unroll
        for (int j = 0; j < 8; j++) {
            float a = dt[j];
            #pragma unroll
            for (int m = 0; m < j; m++) a = fmaf(-G[j * (j - 1) / 2 + m], s[m], a);
            s[j] = a;
        }

        // p_out = p_in - sum_j s_j k_j  (critical path for next group)
        #pragma unroll
        for (int j = 0; j < 8; j++) {
            p.x = fmaf(-s[j], kk[j].x, p.x);
            p.y = fmaf(-s[j], kk[j].y, p.y);
        }
        // Mq accumulation (off critical path)
        #pragma unroll
        for (int j = 0; j < 8; j++) {
            acc.x = fmaf(s[j], vv[j].x, acc.x);
            acc.y = fmaf(s[j], vv[j].y, acc.y);
        }
    }

    // ---- epilogue: out = Wcomb @ (Mq) + bcomb ----
    smq[2 * lane]     = acc.x;
    smq[2 * lane + 1] = acc.y;
    __syncwarp();
    #pragma unroll
    for (int rr = 0; rr < 2; rr++) {
        const int i = lane + 32 * rr;
        const float4* w4 = (const float4*)(g_Wcomb + i * H);
        const float4* m4 = (const float4*)smq;
        float a0 = 0.f, a1 = 0.f, a2 = 0.f, a3 = 0.f;
        #pragma unroll
        for (int j = 0; j < 16; j++) {
            float4 w = w4[j], m = m4[j];
            a0 = fmaf(w.x, m.x, a0); a1 = fmaf(w.y, m.y, a1);
            a2 = fmaf(w.z, m.z, a2); a3 = fmaf(w.w, m.w, a3);
        }
        out[b * H + i] = (a0 + a1) + (a2 + a3) + g_bcomb[i];
    }
}

// ======================================================================
extern "C" void kernel_launch(void* const* d_in, const int* in_sizes, int n_in,
                              void* d_out, int out_size)
{
    (void)in_sizes; (void)n_in; (void)out_size;
    const int*   seq   = (const int*)  d_in[0];
    const float* embed = (const float*)d_in[1];
    const float* W1    = (const float*)d_in[2];
    const float* b1    = (const float*)d_in[3];
    const float* W2    = (const float*)d_in[4];
    const float* b2    = (const float*)d_in[5];
    const float* gamma = (const float*)d_in[6];
    const float* beta  = (const float*)d_in[7];
    const float* Wk    = (const float*)d_in[8];
    const float* Wv    = (const float*)d_in[9];
    const float* Wq    = (const float*)d_in[10];
    const float* Wrp   = (const float*)d_in[11];
    const float* brp   = (const float*)d_in[12];
    const float* Wout  = (const float*)d_in[13];
    const float* bout  = (const float*)d_in[14];

    precompute_tables<<<VOCAB, 128>>>(embed, W1, b1, W2, b2, gamma, beta, Wk, Wv, Wq);
    precompute_misc<<<VOCAB, H>>>(Wrp, brp, Wout, bout);
    scan_kernel<<<NB, 32>>>(seq, (float*)d_out);
}